// round 1
// baseline (speedup 1.0000x reference)
#include <cuda_runtime.h>
#include <math.h>

// ---------------- problem constants ----------------
#define BNUM 32
#define HH   56
#define WW   56
#define CC   192
#define NHH  6
#define HD   32          // CC/NHH
#define WSZ  7
#define SSZ  3
#define NN   49          // WSZ*WSZ
#define NWIN 64          // (HH/WSZ)*(WW/WSZ)
#define TOK  (BNUM*HH*WW)   // 100352
#define HIDD 768            // 4*CC

// ---------------- scratch (device globals; no allocation) ----------------
__device__ float g_xw  [(size_t)TOK*CC];     // LN1 + shifted window partition
__device__ float g_qkv [(size_t)TOK*3*CC];   // qkv projection
__device__ float g_attn[(size_t)TOK*CC];     // attention output (windowed layout)
__device__ float g_proj[(size_t)TOK*CC];     // proj output (windowed layout)
__device__ float g_y   [(size_t)TOK*CC];     // x + attn branch (natural layout)
__device__ float g_xm  [(size_t)TOK*CC];     // LN2 output
__device__ float g_h   [(size_t)TOK*HIDD];   // fc1+GELU output

// ---------------- LayerNorm (warp per token) ----------------
// MODE 0: read x with cyclic shift (-SSZ) + window partition -> g_xw
// MODE 1: read g_y (identity)                                -> g_xm
template<int MODE>
__global__ void ln_kernel(const float* __restrict__ x,
                          const float* __restrict__ gamma,
                          const float* __restrict__ beta)
{
    int warp = (blockIdx.x * blockDim.x + threadIdx.x) >> 5;
    int lane = threadIdx.x & 31;
    if (warp >= TOK) return;

    const float* src;
    float* dst;
    if (MODE == 0) {
        int tw = warp;                 // windowed token id
        int w  = tw / NN, n = tw % NN;
        int bb = w / NWIN, wi = w % NWIN;
        int wrow = wi >> 3, wcol = wi & 7;
        int ih = n / WSZ, iw = n % WSZ;
        int gh = wrow * WSZ + ih + SSZ; if (gh >= HH) gh -= HH;   // xs[h] = xn[h+SS]
        int gw = wcol * WSZ + iw + SSZ; if (gw >= WW) gw -= WW;
        src = x + ((size_t)bb * HH * WW + (size_t)gh * WW + gw) * CC;
        dst = g_xw + (size_t)tw * CC;
    } else {
        src = g_y + (size_t)warp * CC;
        dst = g_xm + (size_t)warp * CC;
    }

    float v[6];
    float s = 0.f;
#pragma unroll
    for (int k = 0; k < 6; k++) { v[k] = src[lane + 32 * k]; s += v[k]; }
#pragma unroll
    for (int o = 16; o; o >>= 1) s += __shfl_xor_sync(0xffffffffu, s, o);
    float mean = s * (1.0f / CC);
    float vs = 0.f;
#pragma unroll
    for (int k = 0; k < 6; k++) { float d = v[k] - mean; vs += d * d; }
#pragma unroll
    for (int o = 16; o; o >>= 1) vs += __shfl_xor_sync(0xffffffffu, vs, o);
    float inv = rsqrtf(vs * (1.0f / CC) + 1e-5f);
#pragma unroll
    for (int k = 0; k < 6; k++) {
        int c = lane + 32 * k;
        dst[c] = (v[k] - mean) * inv * gamma[c] + beta[c];
    }
}

// ---------------- SGEMM: C[M,N] = A[M,K] @ W[K,N] + bias (+GELU / +res) ----
// BM=128, BN=64, BK=16, 256 threads, 8x4 microtile. All dims exact multiples.
template<int ACT, bool RES>
__global__ void __launch_bounds__(256)
gemm_kernel(const float* __restrict__ A,
            const float* __restrict__ W,
            const float* __restrict__ bias,
            const float* __restrict__ res,
            float* __restrict__ C,
            int M, int N, int K)
{
    __shared__ float As[16][128];
    __shared__ float Bs[16][64];

    const int t  = threadIdx.x;
    const int m0 = blockIdx.y * 128;
    const int n0 = blockIdx.x * 64;

    const int la_r = t >> 2;            // 0..63
    const int la_c = (t & 3) << 2;      // 0,4,8,12
    const int lb_r = t >> 4;            // 0..15
    const int lb_c = (t & 15) << 2;     // 0..60
    const int ty = t >> 4;              // 0..15 -> rows ty*8
    const int tx = t & 15;              // 0..15 -> cols tx*4

    float acc[8][4];
#pragma unroll
    for (int i = 0; i < 8; i++)
#pragma unroll
        for (int j = 0; j < 4; j++) acc[i][j] = 0.f;

    for (int k0 = 0; k0 < K; k0 += 16) {
        float4 a0 = *(const float4*)&A[(size_t)(m0 + la_r)      * K + k0 + la_c];
        float4 a1 = *(const float4*)&A[(size_t)(m0 + la_r + 64) * K + k0 + la_c];
        float4 bv = *(const float4*)&W[(size_t)(k0 + lb_r) * N + n0 + lb_c];
        __syncthreads();
        As[la_c + 0][la_r] = a0.x; As[la_c + 1][la_r] = a0.y;
        As[la_c + 2][la_r] = a0.z; As[la_c + 3][la_r] = a0.w;
        As[la_c + 0][la_r + 64] = a1.x; As[la_c + 1][la_r + 64] = a1.y;
        As[la_c + 2][la_r + 64] = a1.z; As[la_c + 3][la_r + 64] = a1.w;
        *(float4*)&Bs[lb_r][lb_c] = bv;
        __syncthreads();
#pragma unroll
        for (int k = 0; k < 16; k++) {
            float a[8], b[4];
            *(float4*)&a[0] = *(const float4*)&As[k][ty * 8];
            *(float4*)&a[4] = *(const float4*)&As[k][ty * 8 + 4];
            *(float4*)&b[0] = *(const float4*)&Bs[k][tx * 4];
#pragma unroll
            for (int i = 0; i < 8; i++)
#pragma unroll
                for (int j = 0; j < 4; j++) acc[i][j] = fmaf(a[i], b[j], acc[i][j]);
        }
    }

    float bb[4];
#pragma unroll
    for (int j = 0; j < 4; j++) bb[j] = bias[n0 + tx * 4 + j];

#pragma unroll
    for (int i = 0; i < 8; i++) {
        size_t r = (size_t)(m0 + ty * 8 + i);
        float4 o;
        float vv[4];
#pragma unroll
        for (int j = 0; j < 4; j++) {
            float v = acc[i][j] + bb[j];
            if (ACT == 1) v = 0.5f * v * (1.0f + erff(v * 0.70710678118654752f));
            vv[j] = v;
        }
        if (RES) {
            float4 rv = *(const float4*)&res[r * N + n0 + tx * 4];
            vv[0] += rv.x; vv[1] += rv.y; vv[2] += rv.z; vv[3] += rv.w;
        }
        o.x = vv[0]; o.y = vv[1]; o.z = vv[2]; o.w = vv[3];
        *(float4*)&C[r * N + n0 + tx * 4] = o;
    }
}

// ---------------- windowed attention: one block per (window, head) --------
__global__ void __launch_bounds__(256)
attn_kernel(const float* __restrict__ rel_bias)
{
    __shared__ float qs[NN * 32];
    __shared__ float ks[NN * 33];       // padded stride -> no bank conflicts
    __shared__ float vs[NN * 32];
    __shared__ float sc[NN * NN];
    __shared__ int   lab[NN];

    const int blk = blockIdx.x;
    const int w = blk / NHH;            // 0..2047
    const int h = blk % NHH;            // 0..5
    const int t = threadIdx.x;

    // load q/k/v tiles for this (window, head)
    for (int e = t; e < NN * HD; e += 256) {
        int n = e >> 5, d = e & 31;
        size_t r = (size_t)(w * NN + n) * (3 * CC);
        qs[e]           = g_qkv[r +           h * HD + d];
        ks[n * 33 + d]  = g_qkv[r + CC      + h * HD + d];
        vs[e]           = g_qkv[r + 2 * CC  + h * HD + d];
    }
    if (t < NN) {
        int wi = w % NWIN;
        int gh = (wi >> 3) * WSZ + t / WSZ;
        int gw = (wi & 7)  * WSZ + t % WSZ;
        int a = (gh < HH - WSZ) ? 0 : ((gh < HH - SSZ) ? 1 : 2);
        int b = (gw < WW - WSZ) ? 0 : ((gw < WW - SSZ) ? 1 : 2);
        lab[t] = a * 3 + b;
    }
    __syncthreads();

    const float scale = 0.17677669529663687f;   // 1/sqrt(32)
    for (int p = t; p < NN * NN; p += 256) {
        int i = p / NN, j = p % NN;
        float dot = 0.f;
#pragma unroll
        for (int d = 0; d < HD; d++) dot = fmaf(qs[i * 32 + d], ks[j * 33 + d], dot);
        int dh = i / WSZ - j / WSZ + (WSZ - 1);
        int dw = i % WSZ - j % WSZ + (WSZ - 1);
        float bias = rel_bias[(dh * (2 * WSZ - 1) + dw) * NHH + h];
        float m = (lab[i] != lab[j]) ? -100.0f : 0.0f;
        sc[p] = dot * scale + bias + m;
    }
    __syncthreads();

    // softmax: warp per row
    int wid = t >> 5, lane = t & 31;
    for (int i = wid; i < NN; i += 8) {
        float v0 = sc[i * NN + lane];
        float v1 = (lane + 32 < NN) ? sc[i * NN + lane + 32] : -1e30f;
        float m = fmaxf(v0, v1);
#pragma unroll
        for (int o = 16; o; o >>= 1) m = fmaxf(m, __shfl_xor_sync(0xffffffffu, m, o));
        float e0 = expf(v0 - m);
        float e1 = (lane + 32 < NN) ? expf(v1 - m) : 0.f;
        float s = e0 + e1;
#pragma unroll
        for (int o = 16; o; o >>= 1) s += __shfl_xor_sync(0xffffffffu, s, o);
        float inv = 1.0f / s;
        sc[i * NN + lane] = e0 * inv;
        if (lane + 32 < NN) sc[i * NN + lane + 32] = e1 * inv;
    }
    __syncthreads();

    // out = attn @ v  -> g_attn in [token, head*32+d] layout
    for (int p = t; p < NN * HD; p += 256) {
        int n = p >> 5, d = p & 31;
        float o = 0.f;
#pragma unroll
        for (int j = 0; j < NN; j++) o = fmaf(sc[n * NN + j], vs[j * 32 + d], o);
        g_attn[(size_t)(w * NN + n) * CC + h * HD + d] = o;
    }
}

// ---------------- window reverse + un-shift + residual --------------------
__global__ void unshift_add_kernel(const float* __restrict__ x)
{
    size_t idx = (size_t)blockIdx.x * blockDim.x + threadIdx.x;
    if (idx >= (size_t)TOK * CC) return;
    int c   = (int)(idx % CC);
    int tok = (int)(idx / CC);
    int pos = tok % (HH * WW), bb = tok / (HH * WW);
    int gh = pos / WW, gw = pos % WW;
    int hp = gh - SSZ; if (hp < 0) hp += HH;    // roll(+SS): out[h] = pre[h-SS]
    int wp = gw - SSZ; if (wp < 0) wp += WW;
    int rw = ((bb * 8 + hp / WSZ) * 8 + wp / WSZ) * NN + (hp % WSZ) * WSZ + (wp % WSZ);
    g_y[idx] = x[idx] + g_proj[(size_t)rw * CC + c];
}

// ---------------- launch ----------------
extern "C" void kernel_launch(void* const* d_in, const int* in_sizes, int n_in,
                              void* d_out, int out_size)
{
    const float* x       = (const float*)d_in[0];
    const float* norm1_g = (const float*)d_in[1];
    const float* norm1_b = (const float*)d_in[2];
    const float* qkv_w   = (const float*)d_in[3];
    const float* qkv_b   = (const float*)d_in[4];
    const float* rel_b   = (const float*)d_in[5];
    const float* proj_w  = (const float*)d_in[6];
    const float* proj_b  = (const float*)d_in[7];
    const float* norm2_g = (const float*)d_in[8];
    const float* norm2_b = (const float*)d_in[9];
    const float* fc1_w   = (const float*)d_in[10];
    const float* fc1_b   = (const float*)d_in[11];
    const float* fc2_w   = (const float*)d_in[12];
    const float* fc2_b   = (const float*)d_in[13];
    float* out = (float*)d_out;

    float *p_xw, *p_qkv, *p_attn, *p_proj, *p_y, *p_xm, *p_h;
    cudaGetSymbolAddress((void**)&p_xw,   g_xw);
    cudaGetSymbolAddress((void**)&p_qkv,  g_qkv);
    cudaGetSymbolAddress((void**)&p_attn, g_attn);
    cudaGetSymbolAddress((void**)&p_proj, g_proj);
    cudaGetSymbolAddress((void**)&p_y,    g_y);
    cudaGetSymbolAddress((void**)&p_xm,   g_xm);
    cudaGetSymbolAddress((void**)&p_h,    g_h);

    const int lnBlocks = TOK / 8;                 // 8 warps/block, warp/token

    // 1) LN1 + shift + window partition
    ln_kernel<0><<<lnBlocks, 256>>>(x, norm1_g, norm1_b);

    // 2) QKV gemm: [TOK,192] x [192,576]
    gemm_kernel<0, false><<<dim3(576 / 64, TOK / 128), 256>>>(
        p_xw, qkv_w, qkv_b, nullptr, p_qkv, TOK, 3 * CC, CC);

    // 3) windowed attention
    attn_kernel<<<(TOK / NN) * NHH, 256>>>(rel_b);

    // 4) proj gemm: [TOK,192] x [192,192]
    gemm_kernel<0, false><<<dim3(CC / 64, TOK / 128), 256>>>(
        p_attn, proj_w, proj_b, nullptr, p_proj, TOK, CC, CC);

    // 5) window reverse + unshift + residual
    unshift_add_kernel<<<(int)(((size_t)TOK * CC + 255) / 256), 256>>>(x);

    // 6) LN2
    ln_kernel<1><<<lnBlocks, 256>>>(nullptr, norm2_g, norm2_b);

    // 7) fc1 + exact GELU: [TOK,192] x [192,768]
    gemm_kernel<1, false><<<dim3(HIDD / 64, TOK / 128), 256>>>(
        p_xm, fc1_w, fc1_b, nullptr, p_h, TOK, HIDD, CC);

    // 8) fc2 + residual -> d_out: [TOK,768] x [768,192]
    gemm_kernel<0, true><<<dim3(CC / 64, TOK / 128), 256>>>(
        p_h, fc2_w, fc2_b, p_y, out, TOK, CC, HIDD);
}

// round 4
// speedup vs baseline: 1.7030x; 1.7030x over previous
#include <cuda_runtime.h>
#include <math.h>
#include <stdint.h>

// ---------------- problem constants ----------------
#define BNUM 32
#define HH   56
#define WW   56
#define CC   192
#define NHH  6
#define HD   32
#define WSZ  7
#define SSZ  3
#define NN   49
#define NWIN 64
#define TOK  (BNUM*HH*WW)   // 100352
#define HIDD 768

// ---------------- scratch ----------------
__device__ float g_xw  [(size_t)TOK*CC];
__device__ float g_qkv [(size_t)TOK*3*CC];
__device__ float g_attn[(size_t)TOK*CC];
__device__ float g_proj[(size_t)TOK*CC];
__device__ float g_y   [(size_t)TOK*CC];
__device__ float g_xm  [(size_t)TOK*CC];
__device__ float g_h   [(size_t)TOK*HIDD];

// ---------------- LayerNorm (warp per token) ----------------
template<int MODE>
__global__ void ln_kernel(const float* __restrict__ x,
                          const float* __restrict__ gamma,
                          const float* __restrict__ beta)
{
    int warp = (blockIdx.x * blockDim.x + threadIdx.x) >> 5;
    int lane = threadIdx.x & 31;
    if (warp >= TOK) return;

    const float* src;
    float* dst;
    if (MODE == 0) {
        int tw = warp;
        int w  = tw / NN, n = tw % NN;
        int bb = w / NWIN, wi = w % NWIN;
        int wrow = wi >> 3, wcol = wi & 7;
        int ih = n / WSZ, iw = n % WSZ;
        int gh = wrow * WSZ + ih + SSZ; if (gh >= HH) gh -= HH;
        int gw = wcol * WSZ + iw + SSZ; if (gw >= WW) gw -= WW;
        src = x + ((size_t)bb * HH * WW + (size_t)gh * WW + gw) * CC;
        dst = g_xw + (size_t)tw * CC;
    } else {
        src = g_y + (size_t)warp * CC;
        dst = g_xm + (size_t)warp * CC;
    }

    float v[6];
    float s = 0.f;
#pragma unroll
    for (int k = 0; k < 6; k++) { v[k] = src[lane + 32 * k]; s += v[k]; }
#pragma unroll
    for (int o = 16; o; o >>= 1) s += __shfl_xor_sync(0xffffffffu, s, o);
    float mean = s * (1.0f / CC);
    float vs = 0.f;
#pragma unroll
    for (int k = 0; k < 6; k++) { float d = v[k] - mean; vs += d * d; }
#pragma unroll
    for (int o = 16; o; o >>= 1) vs += __shfl_xor_sync(0xffffffffu, vs, o);
    float inv = rsqrtf(vs * (1.0f / CC) + 1e-5f);
#pragma unroll
    for (int k = 0; k < 6; k++) {
        int c = lane + 32 * k;
        dst[c] = (v[k] - mean) * inv * gamma[c] + beta[c];
    }
}

// ================= tf32 mma.sync GEMM =================
// C[M,N] = A[M,K] @ W[K,N] (+bias, +GELU, +res)
// BM=128, BN=64, BK=16. 256 threads = 8 warps (4 m x 2 n), warp tile 32x32.
// SMEM: A as [row][k] stride 20 words, B as [k][n] stride 72 words (bank-clean).

#define AS_STRIDE 20
#define BS_STRIDE 72

__device__ __forceinline__ uint32_t f2tf32(float f) {
    uint32_t u;
    asm("cvt.rna.tf32.f32 %0, %1;" : "=r"(u) : "f"(f));
    return u;
}

__device__ __forceinline__ void mma_tf32(float* c, const uint32_t* a, const uint32_t* b) {
    asm volatile(
        "mma.sync.aligned.m16n8k8.row.col.f32.tf32.tf32.f32 "
        "{%0,%1,%2,%3}, {%4,%5,%6,%7}, {%8,%9}, {%0,%1,%2,%3};"
        : "+f"(c[0]), "+f"(c[1]), "+f"(c[2]), "+f"(c[3])
        : "r"(a[0]), "r"(a[1]), "r"(a[2]), "r"(a[3]), "r"(b[0]), "r"(b[1]));
}

template<int ACT, bool RES>
__global__ void __launch_bounds__(256)
gemm_mma(const float* __restrict__ A, const float* __restrict__ W,
         const float* __restrict__ bias, const float* __restrict__ res,
         float* __restrict__ C, int M, int N, int K)
{
    __shared__ uint32_t As[2][128 * AS_STRIDE];
    __shared__ uint32_t Bs[2][16 * BS_STRIDE];

    const int t    = threadIdx.x;
    const int lane = t & 31;
    const int wid  = t >> 5;
    const int wm   = wid & 3;          // warp row group (32 rows each)
    const int wn   = wid >> 2;         // warp col group (32 cols each)
    const int m0   = blockIdx.y << 7;
    const int n0   = blockIdx.x << 6;

    const int T = K >> 4;

    // global load indices
    const int ar0 = t >> 2;            // A rows handled: ar0, ar0+64
    const int ak0 = (t & 3) << 2;      // k group of 4
    const int bk  = t >> 4;            // 0..15
    const int bn0 = (t & 15) << 2;     // 0..60

    float4 ra0, ra1, rb;
    auto g_load = [&](int kt) {
        const int k0 = kt << 4;
        ra0 = *(const float4*)&A[(size_t)(m0 + ar0)      * K + k0 + ak0];
        ra1 = *(const float4*)&A[(size_t)(m0 + ar0 + 64) * K + k0 + ak0];
        rb  = *(const float4*)&W[(size_t)(k0 + bk) * N + n0 + bn0];
    };
    auto s_store = [&](int b) {
        uint32_t* ap = &As[b][ar0 * AS_STRIDE + ak0];
        ap[0] = f2tf32(ra0.x); ap[1] = f2tf32(ra0.y);
        ap[2] = f2tf32(ra0.z); ap[3] = f2tf32(ra0.w);
        uint32_t* ap2 = ap + 64 * AS_STRIDE;
        ap2[0] = f2tf32(ra1.x); ap2[1] = f2tf32(ra1.y);
        ap2[2] = f2tf32(ra1.z); ap2[3] = f2tf32(ra1.w);
        uint32_t* bp = &Bs[b][bk * BS_STRIDE + bn0];
        bp[0] = f2tf32(rb.x); bp[1] = f2tf32(rb.y);
        bp[2] = f2tf32(rb.z); bp[3] = f2tf32(rb.w);
    };

    float acc[2][4][4];
#pragma unroll
    for (int i = 0; i < 2; i++)
#pragma unroll
        for (int j = 0; j < 4; j++)
#pragma unroll
            for (int q = 0; q < 4; q++) acc[i][j][q] = 0.f;

    const int aRow = wm * 32 + (lane >> 2);   // fragment row within tile
    const int aK   = lane & 3;
    const int bN   = wn * 32 + (lane >> 2);
    const int bK   = lane & 3;

    g_load(0);
    s_store(0);
    __syncthreads();

    for (int kt = 0; kt < T; kt++) {
        const int b = kt & 1;
        if (kt + 1 < T) g_load(kt + 1);

#pragma unroll
        for (int kk = 0; kk < 16; kk += 8) {
            uint32_t av[2][4], bv[4][2];
#pragma unroll
            for (int mt = 0; mt < 2; mt++) {
                const uint32_t* p = &As[b][(aRow + mt * 16) * AS_STRIDE + kk + aK];
                av[mt][0] = p[0];
                av[mt][1] = p[8 * AS_STRIDE];
                av[mt][2] = p[4];
                av[mt][3] = p[8 * AS_STRIDE + 4];
            }
#pragma unroll
            for (int nt = 0; nt < 4; nt++) {
                const uint32_t* p = &Bs[b][(kk + bK) * BS_STRIDE + bN - (lane >> 2) + nt * 8 + (lane >> 2)];
                bv[nt][0] = p[0];
                bv[nt][1] = p[4 * BS_STRIDE];
            }
#pragma unroll
            for (int mt = 0; mt < 2; mt++)
#pragma unroll
                for (int nt = 0; nt < 4; nt++)
                    mma_tf32(acc[mt][nt], av[mt], bv[nt]);
        }

        if (kt + 1 < T) {
            __syncthreads();
            s_store((kt + 1) & 1);
            __syncthreads();
        }
    }

    // ---------------- epilogue ----------------
    const int colBase = n0 + wn * 32 + ((lane & 3) << 1);
    const int rowBase = m0 + wm * 32 + (lane >> 2);
#pragma unroll
    for (int mt = 0; mt < 2; mt++) {
#pragma unroll
        for (int half = 0; half < 2; half++) {
            const int r = rowBase + mt * 16 + half * 8;
            float* Crow = C + (size_t)r * N;
            const float* Rrow = res + (size_t)r * N;
#pragma unroll
            for (int nt = 0; nt < 4; nt++) {
                const int c0 = colBase + nt * 8;
                float v0 = acc[mt][nt][half * 2 + 0] + bias[c0];
                float v1 = acc[mt][nt][half * 2 + 1] + bias[c0 + 1];
                if (ACT == 1) {
                    v0 = 0.5f * v0 * (1.0f + erff(v0 * 0.70710678118654752f));
                    v1 = 0.5f * v1 * (1.0f + erff(v1 * 0.70710678118654752f));
                }
                if (RES) {
                    v0 += Rrow[c0];
                    v1 += Rrow[c0 + 1];
                }
                float2 o; o.x = v0; o.y = v1;
                *(float2*)&Crow[c0] = o;
            }
        }
    }
}

// ---------------- windowed attention: one block per (window, head) --------
__global__ void __launch_bounds__(256)
attn_kernel(const float* __restrict__ rel_bias)
{
    __shared__ float qs[NN * 32];
    __shared__ float ks[NN * 33];
    __shared__ float vs[NN * 32];
    __shared__ float sc[NN * NN];
    __shared__ int   lab[NN];

    const int blk = blockIdx.x;
    const int w = blk / NHH;
    const int h = blk % NHH;
    const int t = threadIdx.x;

    for (int e = t; e < NN * HD; e += 256) {
        int n = e >> 5, d = e & 31;
        size_t r = (size_t)(w * NN + n) * (3 * CC);
        qs[e]          = g_qkv[r +          h * HD + d];
        ks[n * 33 + d] = g_qkv[r + CC     + h * HD + d];
        vs[e]          = g_qkv[r + 2 * CC + h * HD + d];
    }
    if (t < NN) {
        int wi = w % NWIN;
        int gh = (wi >> 3) * WSZ + t / WSZ;
        int gw = (wi & 7)  * WSZ + t % WSZ;
        int a = (gh < HH - WSZ) ? 0 : ((gh < HH - SSZ) ? 1 : 2);
        int b = (gw < WW - WSZ) ? 0 : ((gw < WW - SSZ) ? 1 : 2);
        lab[t] = a * 3 + b;
    }
    __syncthreads();

    const float scale = 0.17677669529663687f;
    for (int p = t; p < NN * NN; p += 256) {
        int i = p / NN, j = p % NN;
        float dot = 0.f;
#pragma unroll
        for (int d = 0; d < HD; d++) dot = fmaf(qs[i * 32 + d], ks[j * 33 + d], dot);
        int dh = i / WSZ - j / WSZ + (WSZ - 1);
        int dw = i % WSZ - j % WSZ + (WSZ - 1);
        float bias = rel_bias[(dh * (2 * WSZ - 1) + dw) * NHH + h];
        float m = (lab[i] != lab[j]) ? -100.0f : 0.0f;
        sc[p] = dot * scale + bias + m;
    }
    __syncthreads();

    int wd = t >> 5, lane = t & 31;
    for (int i = wd; i < NN; i += 8) {
        float v0 = sc[i * NN + lane];
        float v1 = (lane + 32 < NN) ? sc[i * NN + lane + 32] : -1e30f;
        float m = fmaxf(v0, v1);
#pragma unroll
        for (int o = 16; o; o >>= 1) m = fmaxf(m, __shfl_xor_sync(0xffffffffu, m, o));
        float e0 = expf(v0 - m);
        float e1 = (lane + 32 < NN) ? expf(v1 - m) : 0.f;
        float s = e0 + e1;
#pragma unroll
        for (int o = 16; o; o >>= 1) s += __shfl_xor_sync(0xffffffffu, s, o);
        float inv = 1.0f / s;
        sc[i * NN + lane] = e0 * inv;
        if (lane + 32 < NN) sc[i * NN + lane + 32] = e1 * inv;
    }
    __syncthreads();

    for (int p = t; p < NN * HD; p += 256) {
        int n = p >> 5, d = p & 31;
        float o = 0.f;
#pragma unroll
        for (int j = 0; j < NN; j++) o = fmaf(sc[n * NN + j], vs[j * 32 + d], o);
        g_attn[(size_t)(w * NN + n) * CC + h * HD + d] = o;
    }
}

// ---------------- window reverse + un-shift + residual --------------------
__global__ void unshift_add_kernel(const float* __restrict__ x)
{
    size_t idx = (size_t)blockIdx.x * blockDim.x + threadIdx.x;
    if (idx >= (size_t)TOK * CC) return;
    int c   = (int)(idx % CC);
    int tok = (int)(idx / CC);
    int pos = tok % (HH * WW), bb = tok / (HH * WW);
    int gh = pos / WW, gw = pos % WW;
    int hp = gh - SSZ; if (hp < 0) hp += HH;
    int wp = gw - SSZ; if (wp < 0) wp += WW;
    int rw = ((bb * 8 + hp / WSZ) * 8 + wp / WSZ) * NN + (hp % WSZ) * WSZ + (wp % WSZ);
    g_y[idx] = x[idx] + g_proj[(size_t)rw * CC + c];
}

// ---------------- launch ----------------
extern "C" void kernel_launch(void* const* d_in, const int* in_sizes, int n_in,
                              void* d_out, int out_size)
{
    const float* x       = (const float*)d_in[0];
    const float* norm1_g = (const float*)d_in[1];
    const float* norm1_b = (const float*)d_in[2];
    const float* qkv_w   = (const float*)d_in[3];
    const float* qkv_b   = (const float*)d_in[4];
    const float* rel_b   = (const float*)d_in[5];
    const float* proj_w  = (const float*)d_in[6];
    const float* proj_b  = (const float*)d_in[7];
    const float* norm2_g = (const float*)d_in[8];
    const float* norm2_b = (const float*)d_in[9];
    const float* fc1_w   = (const float*)d_in[10];
    const float* fc1_b   = (const float*)d_in[11];
    const float* fc2_w   = (const float*)d_in[12];
    const float* fc2_b   = (const float*)d_in[13];
    float* out = (float*)d_out;

    float *p_xw, *p_qkv, *p_attn, *p_proj, *p_y, *p_xm, *p_h;
    cudaGetSymbolAddress((void**)&p_xw,   g_xw);
    cudaGetSymbolAddress((void**)&p_qkv,  g_qkv);
    cudaGetSymbolAddress((void**)&p_attn, g_attn);
    cudaGetSymbolAddress((void**)&p_proj, g_proj);
    cudaGetSymbolAddress((void**)&p_y,    g_y);
    cudaGetSymbolAddress((void**)&p_xm,   g_xm);
    cudaGetSymbolAddress((void**)&p_h,    g_h);

    const int lnBlocks = TOK / 8;

    // 1) LN1 + shift + window partition
    ln_kernel<0><<<lnBlocks, 256>>>(x, norm1_g, norm1_b);

    // 2) QKV gemm [TOK,192]x[192,576]
    gemm_mma<0, false><<<dim3(576 / 64, TOK / 128), 256>>>(
        p_xw, qkv_w, qkv_b, p_xw, p_qkv, TOK, 3 * CC, CC);

    // 3) windowed attention
    attn_kernel<<<(TOK / NN) * NHH, 256>>>(rel_b);

    // 4) proj gemm [TOK,192]x[192,192]
    gemm_mma<0, false><<<dim3(CC / 64, TOK / 128), 256>>>(
        p_attn, proj_w, proj_b, p_attn, p_proj, TOK, CC, CC);

    // 5) window reverse + unshift + residual
    unshift_add_kernel<<<(int)(((size_t)TOK * CC + 255) / 256), 256>>>(x);

    // 6) LN2
    ln_kernel<1><<<lnBlocks, 256>>>(nullptr, norm2_g, norm2_b);

    // 7) fc1 + exact GELU [TOK,192]x[192,768]
    gemm_mma<1, false><<<dim3(HIDD / 64, TOK / 128), 256>>>(
        p_xm, fc1_w, fc1_b, p_xm, p_h, TOK, HIDD, CC);

    // 8) fc2 + residual [TOK,768]x[768,192] -> d_out
    gemm_mma<0, true><<<dim3(CC / 64, TOK / 128), 256>>>(
        p_h, fc2_w, fc2_b, p_y, out, TOK, CC, HIDD);
}

// round 5
// speedup vs baseline: 2.5097x; 1.4737x over previous
#include <cuda_runtime.h>
#include <cuda_bf16.h>
#include <math.h>
#include <stdint.h>

// ---------------- problem constants ----------------
#define BNUM 32
#define HH   56
#define WW   56
#define CC   192
#define NHH  6
#define HD   32
#define WSZ  7
#define SSZ  3
#define NN   49
#define NWIN 64
#define TOK  (BNUM*HH*WW)   // 100352
#define HIDD 768

typedef __nv_bfloat16 bf16;

// ---------------- scratch ----------------
__device__ bf16  g_xw  [(size_t)TOK*CC];      // LN1 out (bf16, windowed layout)
__device__ float g_qkv [(size_t)TOK*3*CC];    // qkv (fp32 for attention math)
__device__ bf16  g_attn[(size_t)TOK*CC];      // attention out (bf16)
__device__ float g_proj[(size_t)TOK*CC];      // proj out (fp32)
__device__ float g_y   [(size_t)TOK*CC];      // x + attn branch (fp32)
__device__ bf16  g_xm  [(size_t)TOK*CC];      // LN2 out (bf16)
__device__ bf16  g_h   [(size_t)TOK*HIDD];    // fc1+GELU out (bf16)
// transposed bf16 weights [N][K]
__device__ bf16  g_wqkv[(size_t)576*192];
__device__ bf16  g_wprj[(size_t)192*192];
__device__ bf16  g_wfc1[(size_t)HIDD*192];
__device__ bf16  g_wfc2[(size_t)192*HIDD];

// ---------------- PTX helpers ----------------
__device__ __forceinline__ uint32_t smem_u32(const void* p) {
    uint32_t a;
    asm("{ .reg .u64 t; cvta.to.shared.u64 t, %1; cvt.u32.u64 %0, t; }"
        : "=r"(a) : "l"(p));
    return a;
}
__device__ __forceinline__ void cp16(uint32_t s, const void* g) {
    asm volatile("cp.async.cg.shared.global [%0], [%1], 16;" :: "r"(s), "l"(g));
}
#define CP_COMMIT() asm volatile("cp.async.commit_group;" ::: "memory")
__device__ __forceinline__ void ldsm4(uint32_t& r0, uint32_t& r1, uint32_t& r2,
                                      uint32_t& r3, uint32_t a) {
    asm volatile("ldmatrix.sync.aligned.m8n8.x4.shared.b16 {%0,%1,%2,%3}, [%4];"
                 : "=r"(r0), "=r"(r1), "=r"(r2), "=r"(r3) : "r"(a));
}
__device__ __forceinline__ void mma_bf16(float* c, const uint32_t* a, const uint32_t* b) {
    asm volatile(
        "mma.sync.aligned.m16n8k16.row.col.f32.bf16.bf16.f32 "
        "{%0,%1,%2,%3}, {%4,%5,%6,%7}, {%8,%9}, {%0,%1,%2,%3};"
        : "+f"(c[0]), "+f"(c[1]), "+f"(c[2]), "+f"(c[3])
        : "r"(a[0]), "r"(a[1]), "r"(a[2]), "r"(a[3]), "r"(b[0]), "r"(b[1]));
}

// ---------------- weight transpose + bf16 convert: W[K,N] -> Wt[N,K] ------
__global__ void wtrans_kernel(const float* __restrict__ W, bf16* __restrict__ Wt,
                              int K, int N)
{
    __shared__ float tile[32][33];
    int k0 = blockIdx.y * 32, n0 = blockIdx.x * 32;
    int tx = threadIdx.x, ty = threadIdx.y;   // 32 x 8
#pragma unroll
    for (int i = 0; i < 32; i += 8)
        tile[ty + i][tx] = W[(size_t)(k0 + ty + i) * N + n0 + tx];
    __syncthreads();
#pragma unroll
    for (int i = 0; i < 32; i += 8)
        Wt[(size_t)(n0 + ty + i) * K + k0 + tx] = __float2bfloat16(tile[tx][ty + i]);
}

// ---------------- LayerNorm (warp per token), bf16 output -----------------
template<int MODE>
__global__ void ln_kernel(const float* __restrict__ x,
                          const float* __restrict__ gamma,
                          const float* __restrict__ beta)
{
    int warp = (blockIdx.x * blockDim.x + threadIdx.x) >> 5;
    int lane = threadIdx.x & 31;
    if (warp >= TOK) return;

    const float* src;
    bf16* dst;
    if (MODE == 0) {
        int tw = warp;
        int w  = tw / NN, n = tw % NN;
        int bb = w / NWIN, wi = w % NWIN;
        int wrow = wi >> 3, wcol = wi & 7;
        int ih = n / WSZ, iw = n % WSZ;
        int gh = wrow * WSZ + ih + SSZ; if (gh >= HH) gh -= HH;
        int gw = wcol * WSZ + iw + SSZ; if (gw >= WW) gw -= WW;
        src = x + ((size_t)bb * HH * WW + (size_t)gh * WW + gw) * CC;
        dst = g_xw + (size_t)tw * CC;
    } else {
        src = g_y + (size_t)warp * CC;
        dst = g_xm + (size_t)warp * CC;
    }

    float v[6];
    float s = 0.f;
#pragma unroll
    for (int k = 0; k < 6; k++) { v[k] = src[lane + 32 * k]; s += v[k]; }
#pragma unroll
    for (int o = 16; o; o >>= 1) s += __shfl_xor_sync(0xffffffffu, s, o);
    float mean = s * (1.0f / CC);
    float vs = 0.f;
#pragma unroll
    for (int k = 0; k < 6; k++) { float d = v[k] - mean; vs += d * d; }
#pragma unroll
    for (int o = 16; o; o >>= 1) vs += __shfl_xor_sync(0xffffffffu, vs, o);
    float inv = rsqrtf(vs * (1.0f / CC) + 1e-5f);
#pragma unroll
    for (int k = 0; k < 6; k++) {
        int c = lane + 32 * k;
        dst[c] = __float2bfloat16((v[k] - mean) * inv * gamma[c] + beta[c]);
    }
}

// ================= bf16 mma GEMM =================
// C[M,N] = A[M,K] @ Wt[N,K]^T (+bias, +GELU, +res)
// BM=128, BN=64, BK=32. 256 threads = 8 warps (4m x 2n), warp tile 32x32.
// SMEM rows padded to 40 bf16 (80 B) -> conflict-free ldmatrix.
// cp.async double buffer.

#define SROW 40              // bf16 elements per smem row (80 B)
#define A_BUF_B (128 * SROW * 2)   // 10240 B
#define B_BUF_B (64  * SROW * 2)   // 5120 B

template<int ACT, bool RES, bool OBF>
__global__ void __launch_bounds__(256)
gemm_bf16(const bf16* __restrict__ A, const bf16* __restrict__ Wt,
          const float* __restrict__ bias, const float* __restrict__ res,
          void* __restrict__ Cv, int M, int N, int K)
{
    __shared__ __align__(16) bf16 As[2][128 * SROW];
    __shared__ __align__(16) bf16 Bs[2][64 * SROW];

    const int t    = threadIdx.x;
    const int lane = t & 31;
    const int wid  = t >> 5;
    const int wm   = wid & 3;
    const int wn   = wid >> 2;
    const int m0   = blockIdx.y << 7;
    const int n0   = blockIdx.x << 6;

    const uint32_t asB = smem_u32(As);
    const uint32_t bsB = smem_u32(Bs);

    const int T = K >> 5;

    // cp.async chunk mapping
    const int a_row = t >> 2, a_kc = (t & 3) << 3;    // 8 bf16 = 16B
    const int b_row = t >> 2, b_kc = (t & 3) << 3;

    auto load_tiles = [&](int kt, int b) {
        const int k0 = kt << 5;
        uint32_t aD = asB + b * A_BUF_B;
        cp16(aD + a_row * 80 + (a_kc << 1),
             A + (size_t)(m0 + a_row) * K + k0 + a_kc);
        cp16(aD + (a_row + 64) * 80 + (a_kc << 1),
             A + (size_t)(m0 + a_row + 64) * K + k0 + a_kc);
        uint32_t bD = bsB + b * B_BUF_B;
        cp16(bD + b_row * 80 + (b_kc << 1),
             Wt + (size_t)(n0 + b_row) * K + k0 + b_kc);
        CP_COMMIT();
    };

    float acc[2][4][4];
#pragma unroll
    for (int i = 0; i < 2; i++)
#pragma unroll
        for (int j = 0; j < 4; j++)
#pragma unroll
            for (int q = 0; q < 4; q++) acc[i][j][q] = 0.f;

    // fragment base addresses
    const uint32_t aFrag = (wm * 32 + (lane & 15)) * 80 + ((lane >> 4) << 4);
    const uint32_t bFrag = (wn * 32 + (lane & 7) + (((lane >> 4) & 1) << 3)) * 80
                           + (((lane >> 3) & 1) << 4);

    load_tiles(0, 0);

    for (int kt = 0; kt < T; kt++) {
        const int b = kt & 1;
        if (kt + 1 < T) {
            load_tiles(kt + 1, b ^ 1);
            asm volatile("cp.async.wait_group 1;" ::: "memory");
        } else {
            asm volatile("cp.async.wait_group 0;" ::: "memory");
        }
        __syncthreads();

        const uint32_t aB = asB + b * A_BUF_B + aFrag;
        const uint32_t bB = bsB + b * B_BUF_B + bFrag;
#pragma unroll
        for (int kk = 0; kk < 2; kk++) {
            uint32_t av[2][4], bv[4][2];
            ldsm4(av[0][0], av[0][1], av[0][2], av[0][3], aB + kk * 32);
            ldsm4(av[1][0], av[1][1], av[1][2], av[1][3], aB + 16 * 80 + kk * 32);
            ldsm4(bv[0][0], bv[0][1], bv[1][0], bv[1][1], bB + kk * 32);
            ldsm4(bv[2][0], bv[2][1], bv[3][0], bv[3][1], bB + 16 * 80 + kk * 32);
#pragma unroll
            for (int mt = 0; mt < 2; mt++)
#pragma unroll
                for (int nt = 0; nt < 4; nt++)
                    mma_bf16(acc[mt][nt], av[mt], bv[nt]);
        }
        __syncthreads();
    }

    // ---------------- epilogue ----------------
    const int colBase = n0 + wn * 32 + ((lane & 3) << 1);
    const int rowBase = m0 + wm * 32 + (lane >> 2);
#pragma unroll
    for (int mt = 0; mt < 2; mt++) {
#pragma unroll
        for (int half = 0; half < 2; half++) {
            const int r = rowBase + mt * 16 + half * 8;
            const float* Rrow = res + (size_t)r * N;
#pragma unroll
            for (int nt = 0; nt < 4; nt++) {
                const int c0 = colBase + nt * 8;
                float v0 = acc[mt][nt][half * 2 + 0] + bias[c0];
                float v1 = acc[mt][nt][half * 2 + 1] + bias[c0 + 1];
                if (ACT == 1) {
                    v0 = 0.5f * v0 * (1.0f + erff(v0 * 0.70710678118654752f));
                    v1 = 0.5f * v1 * (1.0f + erff(v1 * 0.70710678118654752f));
                }
                if (RES) { v0 += Rrow[c0]; v1 += Rrow[c0 + 1]; }
                if (OBF) {
                    bf16* Crow = (bf16*)Cv + (size_t)r * N;
                    *(__nv_bfloat162*)&Crow[c0] = __floats2bfloat162_rn(v0, v1);
                } else {
                    float* Crow = (float*)Cv + (size_t)r * N;
                    float2 o; o.x = v0; o.y = v1;
                    *(float2*)&Crow[c0] = o;
                }
            }
        }
    }
}

// ---------------- windowed attention: one block per (window, head) --------
__global__ void __launch_bounds__(256)
attn_kernel(const float* __restrict__ rel_bias)
{
    __shared__ float qs[NN * 32];
    __shared__ float ks[NN * 33];
    __shared__ float vs[NN * 32];
    __shared__ float sc[NN * NN];
    __shared__ int   lab[NN];

    const int blk = blockIdx.x;
    const int w = blk / NHH;
    const int h = blk % NHH;
    const int t = threadIdx.x;

    for (int e = t; e < NN * HD; e += 256) {
        int n = e >> 5, d = e & 31;
        size_t r = (size_t)(w * NN + n) * (3 * CC);
        qs[e]          = g_qkv[r +          h * HD + d];
        ks[n * 33 + d] = g_qkv[r + CC     + h * HD + d];
        vs[e]          = g_qkv[r + 2 * CC + h * HD + d];
    }
    if (t < NN) {
        int wi = w % NWIN;
        int gh = (wi >> 3) * WSZ + t / WSZ;
        int gw = (wi & 7)  * WSZ + t % WSZ;
        int a = (gh < HH - WSZ) ? 0 : ((gh < HH - SSZ) ? 1 : 2);
        int b = (gw < WW - WSZ) ? 0 : ((gw < WW - SSZ) ? 1 : 2);
        lab[t] = a * 3 + b;
    }
    __syncthreads();

    const float scale = 0.17677669529663687f;
    for (int p = t; p < NN * NN; p += 256) {
        int i = p / NN, j = p % NN;
        float dot = 0.f;
#pragma unroll
        for (int d = 0; d < HD; d++) dot = fmaf(qs[i * 32 + d], ks[j * 33 + d], dot);
        int dh = i / WSZ - j / WSZ + (WSZ - 1);
        int dw = i % WSZ - j % WSZ + (WSZ - 1);
        float bias = rel_bias[(dh * (2 * WSZ - 1) + dw) * NHH + h];
        float m = (lab[i] != lab[j]) ? -100.0f : 0.0f;
        sc[p] = dot * scale + bias + m;
    }
    __syncthreads();

    int wd = t >> 5, lane = t & 31;
    for (int i = wd; i < NN; i += 8) {
        float v0 = sc[i * NN + lane];
        float v1 = (lane + 32 < NN) ? sc[i * NN + lane + 32] : -1e30f;
        float m = fmaxf(v0, v1);
#pragma unroll
        for (int o = 16; o; o >>= 1) m = fmaxf(m, __shfl_xor_sync(0xffffffffu, m, o));
        float e0 = expf(v0 - m);
        float e1 = (lane + 32 < NN) ? expf(v1 - m) : 0.f;
        float s = e0 + e1;
#pragma unroll
        for (int o = 16; o; o >>= 1) s += __shfl_xor_sync(0xffffffffu, s, o);
        float inv = 1.0f / s;
        sc[i * NN + lane] = e0 * inv;
        if (lane + 32 < NN) sc[i * NN + lane + 32] = e1 * inv;
    }
    __syncthreads();

    for (int p = t; p < NN * HD; p += 256) {
        int n = p >> 5, d = p & 31;
        float o = 0.f;
#pragma unroll
        for (int j = 0; j < NN; j++) o = fmaf(sc[n * NN + j], vs[j * 32 + d], o);
        g_attn[(size_t)(w * NN + n) * CC + h * HD + d] = __float2bfloat16(o);
    }
}

// ---------------- window reverse + un-shift + residual --------------------
__global__ void unshift_add_kernel(const float* __restrict__ x)
{
    size_t idx = (size_t)blockIdx.x * blockDim.x + threadIdx.x;
    if (idx >= (size_t)TOK * CC) return;
    int c   = (int)(idx % CC);
    int tok = (int)(idx / CC);
    int pos = tok % (HH * WW), bb = tok / (HH * WW);
    int gh = pos / WW, gw = pos % WW;
    int hp = gh - SSZ; if (hp < 0) hp += HH;
    int wp = gw - SSZ; if (wp < 0) wp += WW;
    int rw = ((bb * 8 + hp / WSZ) * 8 + wp / WSZ) * NN + (hp % WSZ) * WSZ + (wp % WSZ);
    g_y[idx] = x[idx] + g_proj[(size_t)rw * CC + c];
}

// ---------------- launch ----------------
extern "C" void kernel_launch(void* const* d_in, const int* in_sizes, int n_in,
                              void* d_out, int out_size)
{
    const float* x       = (const float*)d_in[0];
    const float* norm1_g = (const float*)d_in[1];
    const float* norm1_b = (const float*)d_in[2];
    const float* qkv_w   = (const float*)d_in[3];
    const float* qkv_b   = (const float*)d_in[4];
    const float* rel_b   = (const float*)d_in[5];
    const float* proj_w  = (const float*)d_in[6];
    const float* proj_b  = (const float*)d_in[7];
    const float* norm2_g = (const float*)d_in[8];
    const float* norm2_b = (const float*)d_in[9];
    const float* fc1_w   = (const float*)d_in[10];
    const float* fc1_b   = (const float*)d_in[11];
    const float* fc2_w   = (const float*)d_in[12];
    const float* fc2_b   = (const float*)d_in[13];
    float* out = (float*)d_out;

    bf16 *p_xw, *p_attn, *p_xm, *p_h, *p_wqkv, *p_wprj, *p_wfc1, *p_wfc2;
    float *p_qkv, *p_proj, *p_y;
    cudaGetSymbolAddress((void**)&p_xw,   g_xw);
    cudaGetSymbolAddress((void**)&p_qkv,  g_qkv);
    cudaGetSymbolAddress((void**)&p_attn, g_attn);
    cudaGetSymbolAddress((void**)&p_proj, g_proj);
    cudaGetSymbolAddress((void**)&p_y,    g_y);
    cudaGetSymbolAddress((void**)&p_xm,   g_xm);
    cudaGetSymbolAddress((void**)&p_h,    g_h);
    cudaGetSymbolAddress((void**)&p_wqkv, g_wqkv);
    cudaGetSymbolAddress((void**)&p_wprj, g_wprj);
    cudaGetSymbolAddress((void**)&p_wfc1, g_wfc1);
    cudaGetSymbolAddress((void**)&p_wfc2, g_wfc2);

    const int lnBlocks = TOK / 8;
    dim3 wtb(32, 8);

    // 0) weight transposes (independent of LN)
    wtrans_kernel<<<dim3(576 / 32, 192 / 32), wtb>>>(qkv_w, p_wqkv, CC, 3 * CC);
    wtrans_kernel<<<dim3(192 / 32, 192 / 32), wtb>>>(proj_w, p_wprj, CC, CC);
    wtrans_kernel<<<dim3(HIDD / 32, 192 / 32), wtb>>>(fc1_w, p_wfc1, CC, HIDD);
    wtrans_kernel<<<dim3(192 / 32, HIDD / 32), wtb>>>(fc2_w, p_wfc2, HIDD, CC);

    // 1) LN1 + shift + window partition (bf16 out)
    ln_kernel<0><<<lnBlocks, 256>>>(x, norm1_g, norm1_b);

    // 2) QKV gemm [TOK,192]x[192,576]
    gemm_bf16<0, false, false><<<dim3(9, TOK / 128), 256>>>(
        p_xw, p_wqkv, qkv_b, nullptr, p_qkv, TOK, 3 * CC, CC);

    // 3) windowed attention (bf16 out)
    attn_kernel<<<(TOK / NN) * NHH, 256>>>(rel_b);

    // 4) proj gemm [TOK,192]x[192,192]
    gemm_bf16<0, false, false><<<dim3(3, TOK / 128), 256>>>(
        p_attn, p_wprj, proj_b, nullptr, p_proj, TOK, CC, CC);

    // 5) window reverse + unshift + residual
    unshift_add_kernel<<<(int)(((size_t)TOK * CC + 255) / 256), 256>>>(x);

    // 6) LN2 (bf16 out)
    ln_kernel<1><<<lnBlocks, 256>>>(nullptr, norm2_g, norm2_b);

    // 7) fc1 + exact GELU [TOK,192]x[192,768] (bf16 out)
    gemm_bf16<1, false, true><<<dim3(12, TOK / 128), 256>>>(
        p_xm, p_wfc1, fc1_b, nullptr, p_h, TOK, HIDD, CC);

    // 8) fc2 + residual [TOK,768]x[768,192] -> d_out (fp32)
    gemm_bf16<0, true, false><<<dim3(3, TOK / 128), 256>>>(
        p_h, p_wfc2, fc2_b, p_y, out, TOK, CC, HIDD);
}

// round 6
// speedup vs baseline: 4.3622x; 1.7381x over previous
#include <cuda_runtime.h>
#include <cuda_bf16.h>
#include <math.h>
#include <stdint.h>

// ---------------- problem constants ----------------
#define BNUM 32
#define HH   56
#define WW   56
#define CC   192
#define NHH  6
#define HD   32
#define WSZ  7
#define SSZ  3
#define NN   49
#define NWIN 64
#define TOK  (BNUM*HH*WW)   // 100352
#define HIDD 768

typedef __nv_bfloat16 bf16;

// ---------------- scratch ----------------
__device__ bf16  g_xw  [(size_t)TOK*CC];      // LN1 out (bf16, windowed)
__device__ bf16  g_qkv [(size_t)TOK*3*CC];    // qkv (bf16)
__device__ bf16  g_attn[(size_t)TOK*CC];      // attention out (bf16, windowed)
__device__ float g_y   [(size_t)TOK*CC];      // x + attn branch (fp32, natural)
__device__ bf16  g_xm  [(size_t)TOK*CC];      // LN2 out (bf16)
__device__ bf16  g_h   [(size_t)TOK*HIDD];    // fc1+GELU out (bf16)
__device__ float g_tab [4*6*49*64];           // bias+mask tables per (edge-class, head)
// transposed bf16 weights [N][K]
__device__ bf16  g_wqkv[(size_t)576*192];
__device__ bf16  g_wprj[(size_t)192*192];
__device__ bf16  g_wfc1[(size_t)HIDD*192];
__device__ bf16  g_wfc2[(size_t)192*HIDD];

// ---------------- PTX helpers ----------------
__device__ __forceinline__ uint32_t smem_u32(const void* p) {
    uint32_t a;
    asm("{ .reg .u64 t; cvta.to.shared.u64 t, %1; cvt.u32.u64 %0, t; }"
        : "=r"(a) : "l"(p));
    return a;
}
__device__ __forceinline__ void cp16(uint32_t s, const void* g) {
    asm volatile("cp.async.cg.shared.global [%0], [%1], 16;" :: "r"(s), "l"(g));
}
#define CP_COMMIT() asm volatile("cp.async.commit_group;" ::: "memory")
__device__ __forceinline__ void ldsm4(uint32_t& r0, uint32_t& r1, uint32_t& r2,
                                      uint32_t& r3, uint32_t a) {
    asm volatile("ldmatrix.sync.aligned.m8n8.x4.shared.b16 {%0,%1,%2,%3}, [%4];"
                 : "=r"(r0), "=r"(r1), "=r"(r2), "=r"(r3) : "r"(a));
}
__device__ __forceinline__ void ldsm4t(uint32_t& r0, uint32_t& r1, uint32_t& r2,
                                       uint32_t& r3, uint32_t a) {
    asm volatile("ldmatrix.sync.aligned.m8n8.x4.trans.shared.b16 {%0,%1,%2,%3}, [%4];"
                 : "=r"(r0), "=r"(r1), "=r"(r2), "=r"(r3) : "r"(a));
}
__device__ __forceinline__ void mma_bf16(float* c, const uint32_t* a, const uint32_t* b) {
    asm volatile(
        "mma.sync.aligned.m16n8k16.row.col.f32.bf16.bf16.f32 "
        "{%0,%1,%2,%3}, {%4,%5,%6,%7}, {%8,%9}, {%0,%1,%2,%3};"
        : "+f"(c[0]), "+f"(c[1]), "+f"(c[2]), "+f"(c[3])
        : "r"(a[0]), "r"(a[1]), "r"(a[2]), "r"(a[3]), "r"(b[0]), "r"(b[1]));
}
__device__ __forceinline__ uint32_t packbf2(float lo, float hi) {
    __nv_bfloat162 h2 = __floats2bfloat162_rn(lo, hi);
    return *reinterpret_cast<uint32_t*>(&h2);
}

// ---------------- weight transpose + bf16 convert: W[K,N] -> Wt[N,K] ------
__global__ void wtrans_kernel(const float* __restrict__ W, bf16* __restrict__ Wt,
                              int K, int N)
{
    __shared__ float tile[32][33];
    int k0 = blockIdx.y * 32, n0 = blockIdx.x * 32;
    int tx = threadIdx.x, ty = threadIdx.y;   // 32 x 8
#pragma unroll
    for (int i = 0; i < 32; i += 8)
        tile[ty + i][tx] = W[(size_t)(k0 + ty + i) * N + n0 + tx];
    __syncthreads();
#pragma unroll
    for (int i = 0; i < 32; i += 8)
        Wt[(size_t)(n0 + ty + i) * K + k0 + tx] = __float2bfloat16(tile[tx][ty + i]);
}

// ---------------- bias+mask table precompute --------------------
// g_tab[(mi*6+h)][i][j] : i<49 rows, j 64 cols (j>=49 -> -1e30)
__global__ void tab_kernel(const float* __restrict__ rel_bias)
{
    int bh = blockIdx.x;              // 0..23 = mi*6 + h
    int mi = bh / 6, h = bh % 6;
    int eh = mi >> 1, ew = mi & 1;
    for (int idx = threadIdx.x; idx < NN * 64; idx += 256) {
        int i = idx >> 6, j = idx & 63;
        float val;
        if (j >= NN) val = -1e30f;
        else {
            int ih = i / WSZ, iw = i % WSZ, jh = j / WSZ, jw = j % WSZ;
            int dh = ih - jh + (WSZ - 1), dw = iw - jw + (WSZ - 1);
            float bias = rel_bias[(dh * (2 * WSZ - 1) + dw) * NHH + h];
            int ai = eh ? (ih < WSZ - SSZ ? 1 : 2) : 0;
            int bi = ew ? (iw < WSZ - SSZ ? 1 : 2) : 0;
            int aj = eh ? (jh < WSZ - SSZ ? 1 : 2) : 0;
            int bj = ew ? (jw < WSZ - SSZ ? 1 : 2) : 0;
            float mask = ((ai * 3 + bi) != (aj * 3 + bj)) ? -100.0f : 0.0f;
            val = bias + mask;
        }
        g_tab[(size_t)bh * (NN * 64) + idx] = val;
    }
}

// ---------------- LayerNorm (warp per token), bf16 output -----------------
template<int MODE>
__global__ void ln_kernel(const float* __restrict__ x,
                          const float* __restrict__ gamma,
                          const float* __restrict__ beta)
{
    int warp = (blockIdx.x * blockDim.x + threadIdx.x) >> 5;
    int lane = threadIdx.x & 31;
    if (warp >= TOK) return;

    const float* src;
    bf16* dst;
    if (MODE == 0) {
        int tw = warp;
        int w  = tw / NN, n = tw % NN;
        int bb = w / NWIN, wi = w % NWIN;
        int wrow = wi >> 3, wcol = wi & 7;
        int ih = n / WSZ, iw = n % WSZ;
        int gh = wrow * WSZ + ih + SSZ; if (gh >= HH) gh -= HH;
        int gw = wcol * WSZ + iw + SSZ; if (gw >= WW) gw -= WW;
        src = x + ((size_t)bb * HH * WW + (size_t)gh * WW + gw) * CC;
        dst = g_xw + (size_t)tw * CC;
    } else {
        src = g_y + (size_t)warp * CC;
        dst = g_xm + (size_t)warp * CC;
    }

    float v[6];
    float s = 0.f;
#pragma unroll
    for (int k = 0; k < 6; k++) { v[k] = src[lane + 32 * k]; s += v[k]; }
#pragma unroll
    for (int o = 16; o; o >>= 1) s += __shfl_xor_sync(0xffffffffu, s, o);
    float mean = s * (1.0f / CC);
    float vs = 0.f;
#pragma unroll
    for (int k = 0; k < 6; k++) { float d = v[k] - mean; vs += d * d; }
#pragma unroll
    for (int o = 16; o; o >>= 1) vs += __shfl_xor_sync(0xffffffffu, vs, o);
    float inv = rsqrtf(vs * (1.0f / CC) + 1e-5f);
#pragma unroll
    for (int k = 0; k < 6; k++) {
        int c = lane + 32 * k;
        dst[c] = __float2bfloat16((v[k] - mean) * inv * gamma[c] + beta[c]);
    }
}

// ================= bf16 mma GEMM =================
// RESM: 0 = none, 1 = plain residual (natural rows), 2 = scatter (window
// reverse + unshift) with residual from x. OBF: bf16 output.
#define SROW 40              // bf16 per smem row (80 B)
#define A_BUF_B (128 * SROW * 2)
#define B_BUF_B (64  * SROW * 2)

template<int ACT, int RESM, bool OBF>
__global__ void __launch_bounds__(256)
gemm_bf16(const bf16* __restrict__ A, const bf16* __restrict__ Wt,
          const float* __restrict__ bias, const float* __restrict__ res,
          void* __restrict__ Cv, int M, int N, int K)
{
    __shared__ __align__(16) bf16 As[2][128 * SROW];
    __shared__ __align__(16) bf16 Bs[2][64 * SROW];

    const int t    = threadIdx.x;
    const int lane = t & 31;
    const int wid  = t >> 5;
    const int wm   = wid & 3;
    const int wn   = wid >> 2;
    const int m0   = blockIdx.y << 7;
    const int n0   = blockIdx.x << 6;

    const uint32_t asB = smem_u32(As);
    const uint32_t bsB = smem_u32(Bs);

    const int T = K >> 5;
    const int a_row = t >> 2, a_kc = (t & 3) << 3;

    auto load_tiles = [&](int kt, int b) {
        const int k0 = kt << 5;
        uint32_t aD = asB + b * A_BUF_B;
        cp16(aD + a_row * 80 + (a_kc << 1),
             A + (size_t)(m0 + a_row) * K + k0 + a_kc);
        cp16(aD + (a_row + 64) * 80 + (a_kc << 1),
             A + (size_t)(m0 + a_row + 64) * K + k0 + a_kc);
        uint32_t bD = bsB + b * B_BUF_B;
        cp16(bD + a_row * 80 + (a_kc << 1),
             Wt + (size_t)(n0 + a_row) * K + k0 + a_kc);
        CP_COMMIT();
    };

    float acc[2][4][4];
#pragma unroll
    for (int i = 0; i < 2; i++)
#pragma unroll
        for (int j = 0; j < 4; j++)
#pragma unroll
            for (int q = 0; q < 4; q++) acc[i][j][q] = 0.f;

    const uint32_t aFrag = (wm * 32 + (lane & 15)) * 80 + ((lane >> 4) << 4);
    const uint32_t bFrag = (wn * 32 + (lane & 7) + (((lane >> 4) & 1) << 3)) * 80
                           + (((lane >> 3) & 1) << 4);

    load_tiles(0, 0);

    for (int kt = 0; kt < T; kt++) {
        const int b = kt & 1;
        if (kt + 1 < T) {
            load_tiles(kt + 1, b ^ 1);
            asm volatile("cp.async.wait_group 1;" ::: "memory");
        } else {
            asm volatile("cp.async.wait_group 0;" ::: "memory");
        }
        __syncthreads();

        const uint32_t aB = asB + b * A_BUF_B + aFrag;
        const uint32_t bB = bsB + b * B_BUF_B + bFrag;
#pragma unroll
        for (int kk = 0; kk < 2; kk++) {
            uint32_t av[2][4], bv[4][2];
            ldsm4(av[0][0], av[0][1], av[0][2], av[0][3], aB + kk * 32);
            ldsm4(av[1][0], av[1][1], av[1][2], av[1][3], aB + 16 * 80 + kk * 32);
            ldsm4(bv[0][0], bv[0][1], bv[1][0], bv[1][1], bB + kk * 32);
            ldsm4(bv[2][0], bv[2][1], bv[3][0], bv[3][1], bB + 16 * 80 + kk * 32);
#pragma unroll
            for (int mt = 0; mt < 2; mt++)
#pragma unroll
                for (int nt = 0; nt < 4; nt++)
                    mma_bf16(acc[mt][nt], av[mt], bv[nt]);
        }
        __syncthreads();
    }

    // ---------------- epilogue ----------------
    const int colBase = n0 + wn * 32 + ((lane & 3) << 1);
    const int rowBase = m0 + wm * 32 + (lane >> 2);
#pragma unroll
    for (int mt = 0; mt < 2; mt++) {
#pragma unroll
        for (int half = 0; half < 2; half++) {
            const int r = rowBase + mt * 16 + half * 8;
            size_t outRow = (size_t)r;
            if (RESM == 2) {
                int wq = r / NN, nq = r % NN;
                int bq = wq >> 6, wiq = wq & 63;
                int gh = (wiq >> 3) * WSZ + nq / WSZ + SSZ; if (gh >= HH) gh -= HH;
                int gw = (wiq & 7)  * WSZ + nq % WSZ + SSZ; if (gw >= WW) gw -= WW;
                outRow = (size_t)bq * (HH * WW) + gh * WW + gw;
            }
            const float* Rrow = res + outRow * N;
#pragma unroll
            for (int nt = 0; nt < 4; nt++) {
                const int c0 = colBase + nt * 8;
                float v0 = acc[mt][nt][half * 2 + 0] + bias[c0];
                float v1 = acc[mt][nt][half * 2 + 1] + bias[c0 + 1];
                if (ACT == 1) {
                    v0 = 0.5f * v0 * (1.0f + erff(v0 * 0.70710678118654752f));
                    v1 = 0.5f * v1 * (1.0f + erff(v1 * 0.70710678118654752f));
                }
                if (RESM != 0) { v0 += Rrow[c0]; v1 += Rrow[c0 + 1]; }
                if (OBF) {
                    bf16* Crow = (bf16*)Cv + outRow * N;
                    *(__nv_bfloat162*)&Crow[c0] = __floats2bfloat162_rn(v0, v1);
                } else {
                    float* Crow = (float*)Cv + outRow * N;
                    float2 o; o.x = v0; o.y = v1;
                    *(float2*)&Crow[c0] = o;
                }
            }
        }
    }
}

// ================= tensor-core windowed attention =================
// One block per (window, head). 4 warps; warp w owns m-tile rows 16w..16w+15.
// S = Q K^T (64x64, 49 valid), softmax in fragments, O = P V.
__global__ void __launch_bounds__(128)
attn_mma_kernel()
{
    __shared__ __align__(16) bf16 Qs[64 * SROW];
    __shared__ __align__(16) bf16 Ks[64 * SROW];
    __shared__ __align__(16) bf16 Vs[64 * SROW];

    const int blk = blockIdx.x;
    const int w = blk / NHH, h = blk % NHH;
    const int t = threadIdx.x;
    const int lane = t & 31, mt = t >> 5;

    const uint32_t qB = smem_u32(Qs), kB = smem_u32(Ks), vB = smem_u32(Vs);

    // zero padding rows 49..63 (stride 40 bf16 = 20 u32)
    for (int i = t; i < 15 * 20; i += 128) {
        int off = (49 + i / 20) * 20 + (i % 20);
        ((uint32_t*)Qs)[off] = 0;
        ((uint32_t*)Ks)[off] = 0;
        ((uint32_t*)Vs)[off] = 0;
    }

    // load Q,K,V [49][32] bf16 (64B rows, 4 chunks of 16B)
    const bf16* base = g_qkv + (size_t)w * NN * (3 * CC) + h * HD;
    for (int i = t; i < NN * 4; i += 128) {
        int r = i >> 2, c = (i & 3) << 3;
        const bf16* src = base + (size_t)r * (3 * CC) + c;
        cp16(qB + r * 80 + (c << 1), src);
        cp16(kB + r * 80 + (c << 1), src + CC);
        cp16(vB + r * 80 + (c << 1), src + 2 * CC);
    }
    CP_COMMIT();
    asm volatile("cp.async.wait_group 0;" ::: "memory");
    __syncthreads();

    // ---- S = Q K^T ----
    float sacc[8][4];
#pragma unroll
    for (int i = 0; i < 8; i++)
#pragma unroll
        for (int q = 0; q < 4; q++) sacc[i][q] = 0.f;

    const uint32_t aAddr = qB + (mt * 16 + (lane & 15)) * 80 + ((lane >> 4) << 4);
    const uint32_t bAddr = kB + ((lane & 7) + (((lane >> 4) & 1) << 3)) * 80
                              + (((lane >> 3) & 1) << 4);
#pragma unroll
    for (int kk = 0; kk < 2; kk++) {
        uint32_t av[4];
        ldsm4(av[0], av[1], av[2], av[3], aAddr + kk * 32);
#pragma unroll
        for (int ng = 0; ng < 4; ng++) {
            uint32_t b0, b1, b2, b3;
            ldsm4(b0, b1, b2, b3, bAddr + ng * 16 * 80 + kk * 32);
            uint32_t bv0[2] = {b0, b1}, bv1[2] = {b2, b3};
            mma_bf16(sacc[2 * ng],     av, bv0);
            mma_bf16(sacc[2 * ng + 1], av, bv1);
        }
    }

    // ---- scale + bias/mask table + softmax (in fragments) ----
    const int wi = w & (NWIN - 1);
    const int mi = (((wi >> 3) == 7) ? 2 : 0) + (((wi & 7) == 7) ? 1 : 0);
    const float* tb = g_tab + (size_t)(mi * NHH + h) * (NN * 64);
    const int r0 = mt * 16 + (lane >> 2);        // rows r0, r0+8
    const float scale = 0.17677669529663687f;    // 1/sqrt(32)

#pragma unroll
    for (int nt = 0; nt < 8; nt++) {
        const int c = nt * 8 + ((lane & 3) << 1);
        float t00 = 0.f, t01 = 0.f, t10 = 0.f, t11 = 0.f;
        if (r0 < NN)     { float2 tt = *(const float2*)&tb[r0 * 64 + c];      t00 = tt.x; t01 = tt.y; }
        if (r0 + 8 < NN) { float2 tt = *(const float2*)&tb[(r0 + 8) * 64 + c]; t10 = tt.x; t11 = tt.y; }
        sacc[nt][0] = sacc[nt][0] * scale + t00;
        sacc[nt][1] = sacc[nt][1] * scale + t01;
        sacc[nt][2] = sacc[nt][2] * scale + t10;
        sacc[nt][3] = sacc[nt][3] * scale + t11;
    }

    float m0 = -1e30f, m1 = -1e30f;
#pragma unroll
    for (int nt = 0; nt < 8; nt++) {
        m0 = fmaxf(m0, fmaxf(sacc[nt][0], sacc[nt][1]));
        m1 = fmaxf(m1, fmaxf(sacc[nt][2], sacc[nt][3]));
    }
    m0 = fmaxf(m0, __shfl_xor_sync(0xffffffffu, m0, 1));
    m0 = fmaxf(m0, __shfl_xor_sync(0xffffffffu, m0, 2));
    m1 = fmaxf(m1, __shfl_xor_sync(0xffffffffu, m1, 1));
    m1 = fmaxf(m1, __shfl_xor_sync(0xffffffffu, m1, 2));

    float s0 = 0.f, s1 = 0.f;
#pragma unroll
    for (int nt = 0; nt < 8; nt++) {
        sacc[nt][0] = __expf(sacc[nt][0] - m0);
        sacc[nt][1] = __expf(sacc[nt][1] - m0);
        sacc[nt][2] = __expf(sacc[nt][2] - m1);
        sacc[nt][3] = __expf(sacc[nt][3] - m1);
        s0 += sacc[nt][0] + sacc[nt][1];
        s1 += sacc[nt][2] + sacc[nt][3];
    }
    s0 += __shfl_xor_sync(0xffffffffu, s0, 1);
    s0 += __shfl_xor_sync(0xffffffffu, s0, 2);
    s1 += __shfl_xor_sync(0xffffffffu, s1, 1);
    s1 += __shfl_xor_sync(0xffffffffu, s1, 2);
    const float i0 = 1.0f / s0, i1 = 1.0f / s1;

    // ---- O = P V ----
    float oacc[4][4];
#pragma unroll
    for (int i = 0; i < 4; i++)
#pragma unroll
        for (int q = 0; q < 4; q++) oacc[i][q] = 0.f;

    const uint32_t vAddr = vB + ((((lane >> 3) & 1) << 3) + (lane & 7)) * 80
                              + (((lane >> 4) & 1) << 4);
#pragma unroll
    for (int kk = 0; kk < 4; kk++) {
        uint32_t pa[4];
        pa[0] = packbf2(sacc[2 * kk][0] * i0,     sacc[2 * kk][1] * i0);
        pa[1] = packbf2(sacc[2 * kk][2] * i1,     sacc[2 * kk][3] * i1);
        pa[2] = packbf2(sacc[2 * kk + 1][0] * i0, sacc[2 * kk + 1][1] * i0);
        pa[3] = packbf2(sacc[2 * kk + 1][2] * i1, sacc[2 * kk + 1][3] * i1);
        uint32_t b0, b1, b2, b3;
        ldsm4t(b0, b1, b2, b3, vAddr + kk * 16 * 80);        // dims 0-15
        { uint32_t bv0[2] = {b0, b1}, bv1[2] = {b2, b3};
          mma_bf16(oacc[0], pa, bv0); mma_bf16(oacc[1], pa, bv1); }
        ldsm4t(b0, b1, b2, b3, vAddr + kk * 16 * 80 + 32);   // dims 16-31
        { uint32_t bv0[2] = {b0, b1}, bv1[2] = {b2, b3};
          mma_bf16(oacc[2], pa, bv0); mma_bf16(oacc[3], pa, bv1); }
    }

    // ---- store O (rows < 49) as bf16, windowed layout ----
    bf16* outB = g_attn + (size_t)w * NN * CC + h * HD;
#pragma unroll
    for (int nt = 0; nt < 4; nt++) {
        const int c = nt * 8 + ((lane & 3) << 1);
        if (r0 < NN)
            *(__nv_bfloat162*)&outB[(size_t)r0 * CC + c] =
                __floats2bfloat162_rn(oacc[nt][0], oacc[nt][1]);
        if (r0 + 8 < NN)
            *(__nv_bfloat162*)&outB[(size_t)(r0 + 8) * CC + c] =
                __floats2bfloat162_rn(oacc[nt][2], oacc[nt][3]);
    }
}

// ---------------- launch ----------------
extern "C" void kernel_launch(void* const* d_in, const int* in_sizes, int n_in,
                              void* d_out, int out_size)
{
    const float* x       = (const float*)d_in[0];
    const float* norm1_g = (const float*)d_in[1];
    const float* norm1_b = (const float*)d_in[2];
    const float* qkv_w   = (const float*)d_in[3];
    const float* qkv_b   = (const float*)d_in[4];
    const float* rel_b   = (const float*)d_in[5];
    const float* proj_w  = (const float*)d_in[6];
    const float* proj_b  = (const float*)d_in[7];
    const float* norm2_g = (const float*)d_in[8];
    const float* norm2_b = (const float*)d_in[9];
    const float* fc1_w   = (const float*)d_in[10];
    const float* fc1_b   = (const float*)d_in[11];
    const float* fc2_w   = (const float*)d_in[12];
    const float* fc2_b   = (const float*)d_in[13];
    float* out = (float*)d_out;

    bf16 *p_xw, *p_qkv, *p_attn, *p_xm, *p_h, *p_wqkv, *p_wprj, *p_wfc1, *p_wfc2;
    float *p_y;
    cudaGetSymbolAddress((void**)&p_xw,   g_xw);
    cudaGetSymbolAddress((void**)&p_qkv,  g_qkv);
    cudaGetSymbolAddress((void**)&p_attn, g_attn);
    cudaGetSymbolAddress((void**)&p_y,    g_y);
    cudaGetSymbolAddress((void**)&p_xm,   g_xm);
    cudaGetSymbolAddress((void**)&p_h,    g_h);
    cudaGetSymbolAddress((void**)&p_wqkv, g_wqkv);
    cudaGetSymbolAddress((void**)&p_wprj, g_wprj);
    cudaGetSymbolAddress((void**)&p_wfc1, g_wfc1);
    cudaGetSymbolAddress((void**)&p_wfc2, g_wfc2);

    const int lnBlocks = TOK / 8;
    dim3 wtb(32, 8);

    // 0) weight transposes + bias/mask tables
    wtrans_kernel<<<dim3(576 / 32, 192 / 32), wtb>>>(qkv_w, p_wqkv, CC, 3 * CC);
    wtrans_kernel<<<dim3(192 / 32, 192 / 32), wtb>>>(proj_w, p_wprj, CC, CC);
    wtrans_kernel<<<dim3(HIDD / 32, 192 / 32), wtb>>>(fc1_w, p_wfc1, CC, HIDD);
    wtrans_kernel<<<dim3(192 / 32, HIDD / 32), wtb>>>(fc2_w, p_wfc2, HIDD, CC);
    tab_kernel<<<24, 256>>>(rel_b);

    // 1) LN1 + shift + window partition (bf16)
    ln_kernel<0><<<lnBlocks, 256>>>(x, norm1_g, norm1_b);

    // 2) QKV gemm [TOK,192]x[192,576] -> bf16
    gemm_bf16<0, 0, true><<<dim3(9, TOK / 128), 256>>>(
        p_xw, p_wqkv, qkv_b, nullptr, p_qkv, TOK, 3 * CC, CC);

    // 3) tensor-core windowed attention
    attn_mma_kernel<<<(TOK / NN) * NHH, 128>>>();

    // 4) proj gemm + window-reverse/unshift scatter + residual -> g_y (fp32)
    gemm_bf16<0, 2, false><<<dim3(3, TOK / 128), 256>>>(
        p_attn, p_wprj, proj_b, x, p_y, TOK, CC, CC);

    // 5) LN2 (bf16)
    ln_kernel<1><<<lnBlocks, 256>>>(nullptr, norm2_g, norm2_b);

    // 6) fc1 + exact GELU [TOK,192]x[192,768] -> bf16
    gemm_bf16<1, 0, true><<<dim3(12, TOK / 128), 256>>>(
        p_xm, p_wfc1, fc1_b, nullptr, p_h, TOK, HIDD, CC);

    // 7) fc2 + residual [TOK,768]x[768,192] -> d_out (fp32)
    gemm_bf16<0, 1, false><<<dim3(3, TOK / 128), 256>>>(
        p_h, p_wfc2, fc2_b, p_y, out, TOK, CC, HIDD);
}